// round 3
// baseline (speedup 1.0000x reference)
#include <cuda_runtime.h>
#include <cuda_bf16.h>
#include <math.h>

// ---------------- static problem config ----------------
#define B_ROWS 32768
#define D_COLS 496
#define F_FEAT 40
#define T_STEPS 1000
#define NTHREADS 128
#define D_VEC4 124          // 496 / 4

// log(1e-30f) in f32
#define LNEG (-69.07755279f)

// ---------------- device-global scratch (no allocs allowed) ----------------
__device__ float g_log_alpha[T_STEPS];
__device__ float g_log_1m_alpha[T_STEPS];
__device__ float g_log_ca[T_STEPS];
__device__ float g_log_1m_ca[T_STEPS];
__device__ float g_colsumW[D_COLS];
__device__ float g_partial[B_ROWS];

// log(2),log(4),log(8),log(16),log(32) correctly rounded to f32
__constant__ float c_lognc[5] = {
    0.69314718055994530942f,
    1.38629436111989061883f,
    2.07944154167983592825f,
    2.77258872223978123767f,
    3.46573590279972654709f
};

// ---------------- helpers ----------------
// jnp.logaddexp numerics: max + log1p(exp(-|a-b|))
__device__ __forceinline__ float lap(float a, float b) {
    float m = fmaxf(a, b);
    return m + log1pf(expf(-fabsf(a - b)));
}

// column -> (feature index, log(num_classes)); pattern: 8 groups of width 62,
// each group = segments of size 2,4,8,16,32 (feature k -> start (2<<k)-2)
__device__ __forceinline__ void colinfo(int c, int& feat, float& lognc) {
    int g = c / 62;
    int r = c - g * 62;
    int k = (r >= 30) ? 4 : (r >= 14) ? 3 : (r >= 6) ? 2 : (r >= 2) ? 1 : 0;
    feat = g * 5 + k;
    lognc = c_lognc[k];
}

__device__ __forceinline__ void featinfo(int f, int& segstart, int& nc) {
    int g = f / 5;
    int k = f - g * 5;
    segstart = g * 62 + (2 << k) - 2;
    nc = 2 << k;
}

// ---------------- init: diffusion schedules (f64, matching numpy) ----------------
__global__ void init_sched_kernel() {
    __shared__ double s[1024];
    int t = threadIdx.x;
    double la = 0.0;
    if (t < T_STEPS) {
        // np.linspace(1e-4, 0.02, 1000)
        double beta = 1e-4 + (0.02 - 1e-4) * ((double)t / (double)(T_STEPS - 1));
        double alpha = 1.0 - beta;
        la = log(alpha);
        g_log_alpha[t]    = (float)la;
        g_log_1m_alpha[t] = (float)log(1.0 - alpha);
    }
    s[t] = (t < T_STEPS) ? la : 0.0;
    __syncthreads();
    // inclusive Hillis-Steele scan over log(alpha) -> log cumprod
    for (int off = 1; off < 1024; off <<= 1) {
        double v = (t >= off) ? s[t - off] : 0.0;
        __syncthreads();
        s[t] += v;
        __syncthreads();
    }
    if (t < T_STEPS) {
        double cs = s[t];                 // log(cumprod(alpha)) in f64
        g_log_ca[t]    = (float)cs;
        g_log_1m_ca[t] = (float)log(-expm1(cs));   // log(1 - ca)
    }
}

// ---------------- init: column sums of W ----------------
// grid = 124 blocks, 128 threads; block g owns float4 column-group [4g,4g+4)
__global__ void init_colsum_kernel(const float* __restrict__ W) {
    __shared__ float4 sb[NTHREADS];
    int g4 = blockIdx.x * 4;
    int tid = threadIdx.x;
    float4 acc = make_float4(0.f, 0.f, 0.f, 0.f);
    for (int r = tid; r < D_COLS; r += NTHREADS) {
        float4 v = *reinterpret_cast<const float4*>(W + (size_t)r * D_COLS + g4);
        acc.x += v.x; acc.y += v.y; acc.z += v.z; acc.w += v.w;
    }
    sb[tid] = acc;
    __syncthreads();
    for (int off = NTHREADS / 2; off > 0; off >>= 1) {
        if (tid < off) {
            float4 o = sb[tid + off];
            sb[tid].x += o.x; sb[tid].y += o.y; sb[tid].z += o.z; sb[tid].w += o.w;
        }
        __syncthreads();
    }
    if (tid == 0) {
        *reinterpret_cast<float4*>(g_colsumW + g4) = sb[0];
    }
}

// ---------------- main: one block per batch row ----------------
__global__ __launch_bounds__(NTHREADS) void ddpm_row_kernel(
    const int*   __restrict__ x0,       // [B,F]
    const int*   __restrict__ ts,       // [B]
    const float* __restrict__ uni,      // [B,D]
    const float* __restrict__ W,        // [D,D]
    const float* __restrict__ bvec,     // [D]
    const float* __restrict__ temb)     // [T,D]
{
    __shared__ float Z[D_COLS];   // z (gumbel+logits), later U1 (un_true)
    __shared__ float P[D_COLS];   // pred, later U2 (un_est)
    __shared__ int   sx0[F_FEAT]; // global hot column of x_0 per feature
    __shared__ int   sxt[F_FEAT]; // global hot column of x_t per feature
    __shared__ float fl_pred[F_FEAT];  // seg lse of pred
    __shared__ float fl_u1[F_FEAT];    // seg lse of un_true
    __shared__ float fl_u2[F_FEAT];    // seg lse of un_est
    __shared__ float rbuf[3][NTHREADS / 32];

    const int row = blockIdx.x;
    const int tid = threadIdx.x;

    const int t   = ts[row];
    const int tm1 = max(t - 1, 0);
    const float la_t   = g_log_alpha[t];
    const float l1a_t  = g_log_1m_alpha[t];
    const float lca_t  = g_log_ca[t];
    const float l1ca_t = g_log_1m_ca[t];
    const float lca_m  = g_log_ca[tm1];
    const float l1ca_m = g_log_1m_ca[tm1];
    const float lca_T  = g_log_ca[T_STEPS - 1];
    const float l1ca_T = g_log_1m_ca[T_STEPS - 1];
    const bool  t0 = (t == 0);

    if (tid < F_FEAT) {
        int st, nc;
        featinfo(tid, st, nc);
        sx0[tid] = st + x0[row * F_FEAT + tid];
    }
    __syncthreads();

    // ---- pass 1: z = gumbel + q_prior(log_x0, t) ----
    for (int c = tid; c < D_COLS; c += NTHREADS) {
        int feat; float lognc;
        colinfo(c, feat, lognc);
        float lx0 = (c == sx0[feat]) ? 0.f : LNEG;
        float lp = lap(lx0 + lca_t, l1ca_t - lognc);
        float u = uni[(size_t)row * D_COLS + c];
        float gmb = -logf(-logf(u + 1e-30f) + 1e-30f);
        Z[c] = gmb + lp;
    }
    __syncthreads();

    // ---- pass 2: per-segment first-max argmax (reference tie-break) ----
    if (tid < F_FEAT) {
        int st, nc;
        featinfo(tid, st, nc);
        float best = Z[st];
        int bi = st;
        for (int i = 1; i < nc; ++i) {
            float v = Z[st + i];
            if (v > best) { best = v; bi = st + i; }
        }
        sxt[tid] = bi;
    }
    __syncthreads();

    // ---- pass 3: pred = L*(colsumW - sum_f W[hot_f,:]) + b + t_emb[t] ----
    // float4-vectorized: W rows are 1984 B = 124 x 16 B, always 16B-aligned.
    if (tid < D_VEC4) {
        float4 acc = make_float4(0.f, 0.f, 0.f, 0.f);
        #pragma unroll 8
        for (int f = 0; f < F_FEAT; ++f) {
            float4 v = *reinterpret_cast<const float4*>(
                W + (size_t)sxt[f] * D_COLS + tid * 4);
            acc.x += v.x; acc.y += v.y; acc.z += v.z; acc.w += v.w;
        }
        float4 cs = *reinterpret_cast<const float4*>(g_colsumW + tid * 4);
        float4 bb = *reinterpret_cast<const float4*>(bvec + tid * 4);
        float4 tt = *reinterpret_cast<const float4*>(
            temb + (size_t)t * D_COLS + tid * 4);
        P[tid * 4 + 0] = LNEG * (cs.x - acc.x) + bb.x + tt.x;
        P[tid * 4 + 1] = LNEG * (cs.y - acc.y) + bb.y + tt.y;
        P[tid * 4 + 2] = LNEG * (cs.z - acc.z) + bb.z + tt.z;
        P[tid * 4 + 3] = LNEG * (cs.w - acc.w) + bb.w + tt.w;
    }
    __syncthreads();

    // ---- pass 4: seg logsumexp(pred) ----
    if (tid < F_FEAT) {
        int st, nc;
        featinfo(tid, st, nc);
        float m = P[st];
        for (int i = 1; i < nc; ++i) m = fmaxf(m, P[st + i]);
        float s = 0.f;
        for (int i = 0; i < nc; ++i) s += expf(P[st + i] - m);
        fl_pred[tid] = m + logf(s);
    }
    __syncthreads();

    // ---- pass 5: un_true -> Z, un_est -> P ----
    for (int c = tid; c < D_COLS; c += NTHREADS) {
        int feat; float lognc;
        colinfo(c, feat, lognc);
        float lxt = (c == sxt[feat]) ? 0.f : LNEG;
        float qone = lap(lxt + la_t, l1a_t - lognc);
        float lx0 = (c == sx0[feat]) ? 0.f : LNEG;
        float x0h = P[c] - fl_pred[feat];   // log_x0_hat (per-segment log_softmax)
        float evT = t0 ? lx0 : lap(lx0 + lca_m, l1ca_m - lognc);
        float evE = t0 ? x0h : lap(x0h + lca_m, l1ca_m - lognc);
        Z[c] = evT + qone;
        P[c] = evE + qone;
    }
    __syncthreads();

    // ---- pass 6: seg lse of both un arrays ----
    if (tid < F_FEAT) {
        int st, nc;
        featinfo(tid, st, nc);
        float m1 = Z[st], m2 = P[st];
        for (int i = 1; i < nc; ++i) {
            m1 = fmaxf(m1, Z[st + i]);
            m2 = fmaxf(m2, P[st + i]);
        }
        float s1 = 0.f, s2 = 0.f;
        for (int i = 0; i < nc; ++i) {
            s1 += expf(Z[st + i] - m1);
            s2 += expf(P[st + i] - m2);
        }
        fl_u1[tid] = m1 + logf(s1);
        fl_u2[tid] = m2 + logf(s2);
    }
    __syncthreads();

    // ---- pass 7: kl, dec_nll, kl_prior accumulation ----
    float kl = 0.f, dec = 0.f, kp = 0.f;
    for (int c = tid; c < D_COLS; c += NTHREADS) {
        int feat; float lognc;
        colinfo(c, feat, lognc);
        float lt = Z[c] - fl_u1[feat];   // log_true
        float le = P[c] - fl_u2[feat];   // log_est
        kl += expf(lt) * (lt - le);
        float lx0 = (c == sx0[feat]) ? 0.f : LNEG;
        dec += expf(lx0) * le;
        float lqT = lap(lx0 + lca_T, l1ca_T - lognc);
        kp += expf(lqT) * (lqT + lognc);
    }
    // block reduce (deterministic)
    #pragma unroll
    for (int o = 16; o > 0; o >>= 1) {
        kl  += __shfl_down_sync(0xffffffffu, kl, o);
        dec += __shfl_down_sync(0xffffffffu, dec, o);
        kp  += __shfl_down_sync(0xffffffffu, kp, o);
    }
    if ((tid & 31) == 0) {
        rbuf[0][tid >> 5] = kl;
        rbuf[1][tid >> 5] = dec;
        rbuf[2][tid >> 5] = kp;
    }
    __syncthreads();
    if (tid == 0) {
        float tkl = 0.f, tdec = 0.f, tkp = 0.f;
        #pragma unroll
        for (int w = 0; w < NTHREADS / 32; ++w) {
            tkl += rbuf[0][w]; tdec += rbuf[1][w]; tkp += rbuf[2][w];
        }
        float diff_loss = t0 ? (-tdec) : tkl;
        g_partial[row] = diff_loss * (float)T_STEPS + tkp;
    }
}

// ---------------- final deterministic mean reduction ----------------
__global__ void reduce_kernel(float* __restrict__ out) {
    __shared__ float s[1024];
    int tid = threadIdx.x;
    float acc = 0.f;
    for (int i = tid; i < B_ROWS; i += 1024) acc += g_partial[i];
    s[tid] = acc;
    __syncthreads();
    for (int off = 512; off > 0; off >>= 1) {
        if (tid < off) s[tid] += s[tid + off];
        __syncthreads();
    }
    if (tid == 0) out[0] = s[0] / (float)B_ROWS;
}

// ---------------- launch ----------------
extern "C" void kernel_launch(void* const* d_in, const int* in_sizes, int n_in,
                              void* d_out, int out_size) {
    // Identify inputs robustly by element count (all sizes distinct).
    const int*   x0   = nullptr;  // 32768*40
    const int*   ts   = nullptr;  // 32768
    const float* uni  = nullptr;  // 32768*496
    const float* W    = nullptr;  // 496*496
    const float* bvec = nullptr;  // 496
    const float* temb = nullptr;  // 1000*496
    for (int i = 0; i < n_in; ++i) {
        switch (in_sizes[i]) {
            case B_ROWS * F_FEAT:   x0   = (const int*)d_in[i];   break;
            case B_ROWS:            ts   = (const int*)d_in[i];   break;
            case B_ROWS * D_COLS:   uni  = (const float*)d_in[i]; break;
            case D_COLS * D_COLS:   W    = (const float*)d_in[i]; break;
            case D_COLS:            bvec = (const float*)d_in[i]; break;
            case T_STEPS * D_COLS:  temb = (const float*)d_in[i]; break;
            default: break;
        }
    }
    float* out = (float*)d_out;

    init_sched_kernel<<<1, 1024>>>();
    init_colsum_kernel<<<D_COLS / 4, NTHREADS>>>(W);
    ddpm_row_kernel<<<B_ROWS, NTHREADS>>>(x0, ts, uni, W, bvec, temb);
    reduce_kernel<<<1, 1024>>>(out);
}

// round 5
// speedup vs baseline: 1.1818x; 1.1818x over previous
#include <cuda_runtime.h>
#include <cuda_bf16.h>
#include <cuda_fp16.h>
#include <math.h>

// ---------------- static problem config ----------------
#define B_ROWS 32768
#define D_COLS 496
#define F_FEAT 40
#define T_STEPS 1000
#define NTHREADS 128
#define D_VEC4 124          // 496 / 4

// log(1e-30f) in f32
#define LNEG (-69.07755279f)

// ---------------- device-global scratch (no allocs allowed) ----------------
__device__ float g_log_alpha[T_STEPS];
__device__ float g_log_1m_alpha[T_STEPS];
__device__ float g_log_ca[T_STEPS];
__device__ float g_log_1m_ca[T_STEPS];
__device__ float g_colsumW[D_COLS];
__device__ float g_partial[B_ROWS];
__device__ float g_kp_const;                          // constant part of kl_prior
__device__ __align__(16) __half g_Whalf[D_COLS * D_COLS];   // fp16 copy of W (492 KB)

// log(2),log(4),log(8),log(16),log(32) correctly rounded to f32
__constant__ float c_lognc[5] = {
    0.69314718055994530942f,
    1.38629436111989061883f,
    2.07944154167983592825f,
    2.77258872223978123767f,
    3.46573590279972654709f
};

// ---------------- helpers ----------------
// jnp.logaddexp numerics: max + log1p(exp(-|a-b|))
__device__ __forceinline__ float lap(float a, float b) {
    float m = fmaxf(a, b);
    return m + log1pf(expf(-fabsf(a - b)));
}

// column -> (feature index, log(num_classes)); pattern: 8 groups of width 62,
// each group = segments of size 2,4,8,16,32 (feature k -> start (2<<k)-2)
__device__ __forceinline__ void colinfo(int c, int& feat, float& lognc) {
    int g = c / 62;
    int r = c - g * 62;
    int k = (r >= 30) ? 4 : (r >= 14) ? 3 : (r >= 6) ? 2 : (r >= 2) ? 1 : 0;
    feat = g * 5 + k;
    lognc = c_lognc[k];
}

__device__ __forceinline__ void featinfo(int f, int& segstart, int& nc, int& k) {
    int g = f / 5;
    k = f - g * 5;
    segstart = g * 62 + (2 << k) - 2;
    nc = 2 << k;
}

// ---------------- init: diffusion schedules (f64, matching numpy) ----------------
__global__ void init_sched_kernel() {
    __shared__ double s[1024];
    int t = threadIdx.x;
    double la = 0.0;
    if (t < T_STEPS) {
        // np.linspace(1e-4, 0.02, 1000)
        double beta = 1e-4 + (0.02 - 1e-4) * ((double)t / (double)(T_STEPS - 1));
        double alpha = 1.0 - beta;
        la = log(alpha);
        g_log_alpha[t]    = (float)la;
        g_log_1m_alpha[t] = (float)log(1.0 - alpha);
    }
    s[t] = (t < T_STEPS) ? la : 0.0;
    __syncthreads();
    // inclusive Hillis-Steele scan over log(alpha) -> log cumprod
    for (int off = 1; off < 1024; off <<= 1) {
        double v = (t >= off) ? s[t - off] : 0.0;
        __syncthreads();
        s[t] += v;
        __syncthreads();
    }
    if (t < T_STEPS) {
        double cs = s[t];                 // log(cumprod(alpha)) in f64
        g_log_ca[t]    = (float)cs;
        g_log_1m_ca[t] = (float)log(-expm1(cs));   // log(1 - ca)
    }
    __syncthreads();
    if (t == 0) {
        // constant (non-hot) part of kl_prior: per k, 8 features x (nc-1) cols,
        // each contributing exp(l1caT - lognc) * l1caT   (lognc cancels in the sum term)
        float l1caT = g_log_1m_ca[T_STEPS - 1];
        float acc = 0.f;
        #pragma unroll
        for (int k = 0; k < 5; ++k) {
            int nc = 2 << k;
            acc += 8.f * (float)(nc - 1) * expf(l1caT - c_lognc[k]) * l1caT;
        }
        g_kp_const = acc;
    }
}

// ---------------- init: fp16 copy of W ----------------
__global__ void init_whalf_kernel(const float* __restrict__ W) {
    int i = (blockIdx.x * blockDim.x + threadIdx.x) * 4;
    if (i < D_COLS * D_COLS) {
        float4 v = *reinterpret_cast<const float4*>(W + i);
        __half2 a = __floats2half2_rn(v.x, v.y);
        __half2 b = __floats2half2_rn(v.z, v.w);
        *reinterpret_cast<__half2*>(&g_Whalf[i])     = a;
        *reinterpret_cast<__half2*>(&g_Whalf[i + 2]) = b;
    }
}

// ---------------- init: column sums of W (fp32) ----------------
__global__ void init_colsum_kernel(const float* __restrict__ W) {
    __shared__ float4 sb[NTHREADS];
    int g4 = blockIdx.x * 4;
    int tid = threadIdx.x;
    float4 acc = make_float4(0.f, 0.f, 0.f, 0.f);
    for (int r = tid; r < D_COLS; r += NTHREADS) {
        float4 v = *reinterpret_cast<const float4*>(W + (size_t)r * D_COLS + g4);
        acc.x += v.x; acc.y += v.y; acc.z += v.z; acc.w += v.w;
    }
    sb[tid] = acc;
    __syncthreads();
    for (int off = NTHREADS / 2; off > 0; off >>= 1) {
        if (tid < off) {
            float4 o = sb[tid + off];
            sb[tid].x += o.x; sb[tid].y += o.y; sb[tid].z += o.z; sb[tid].w += o.w;
        }
        __syncthreads();
    }
    if (tid == 0) {
        *reinterpret_cast<float4*>(g_colsumW + g4) = sb[0];
    }
}

// ---------------- main: one block per batch row ----------------
__global__ __launch_bounds__(NTHREADS) void ddpm_row_kernel(
    const int*   __restrict__ x0,       // [B,F]
    const int*   __restrict__ ts,       // [B]
    const float* __restrict__ uni,      // [B,D]
    const float* __restrict__ bvec,     // [D]
    const float* __restrict__ temb)     // [T,D]
{
    __shared__ float Z[D_COLS];          // gumbel z
    __shared__ float P[D_COLS];          // pred, later U2 (un_est)
    __shared__ int   sx0[F_FEAT];
    __shared__ int   sxt[F_FEAT];
    __shared__ float s_hot1[F_FEAT];     // hot q_prior value
    __shared__ float s_qh[F_FEAT];       // hot q_one value
    __shared__ float s_kpf[F_FEAT];      // hot kl_prior term
    __shared__ float s_ltT[F_FEAT], s_pT[F_FEAT];   // log_true / exp at hot-xt col
    __shared__ float s_lt0[F_FEAT], s_p0[F_FEAT];   // at hot-x0 col
    __shared__ float s_ltN[F_FEAT], s_pN[F_FEAT];   // at plain cols
    __shared__ float fl_pred[F_FEAT];    // seg lse of pred
    __shared__ float fl_u2[F_FEAT];      // seg lse of un_est
    __shared__ float s_dec[F_FEAT];      // per-feature dec term
    __shared__ float rbuf[NTHREADS / 32];

    const int row = blockIdx.x;
    const int tid = threadIdx.x;

    const int t   = ts[row];
    const int tm1 = max(t - 1, 0);
    const float la_t   = g_log_alpha[t];
    const float l1a_t  = g_log_1m_alpha[t];
    const float lca_t  = g_log_ca[t];
    const float l1ca_t = g_log_1m_ca[t];
    const float lca_m  = g_log_ca[tm1];
    const float l1ca_m = g_log_1m_ca[tm1];
    const float lca_T  = g_log_ca[T_STEPS - 1];
    const float l1ca_T = g_log_1m_ca[T_STEPS - 1];
    const bool  t0 = (t == 0);

    if (tid < F_FEAT) {
        int st, nc, k;
        featinfo(tid, st, nc, k);
        float lognc = c_lognc[k];
        sx0[tid] = st + x0[row * F_FEAT + tid];
        // hot-column values (non-hot collapse exactly to b = l1ca - lognc, since
        // exp((LNEG + lca) - b) underflows and log1pf of it is exactly 0 in f32)
        s_hot1[tid] = lap(lca_t, l1ca_t - lognc);
        s_qh[tid]   = lap(la_t,  l1a_t  - lognc);
        float lqh = lap(lca_T, l1ca_T - lognc);
        s_kpf[tid] = expf(lqh) * (lqh + lognc);
    }
    __syncthreads();

    // ---- pass 1: z = gumbel + q_prior(log_x0, t) ----
    for (int c = tid; c < D_COLS; c += NTHREADS) {
        int feat; float lognc;
        colinfo(c, feat, lognc);
        float lp = (c == sx0[feat]) ? s_hot1[feat] : (l1ca_t - lognc);
        float u = uni[(size_t)row * D_COLS + c];
        float gmb = -logf(-logf(u + 1e-30f) + 1e-30f);
        Z[c] = gmb + lp;
    }
    __syncthreads();

    // ---- pass 2: per-segment first-max argmax (reference tie-break) ----
    if (tid < F_FEAT) {
        int st, nc, k;
        featinfo(tid, st, nc, k);
        float best = Z[st];
        int bi = st;
        for (int i = 1; i < nc; ++i) {
            float v = Z[st + i];
            if (v > best) { best = v; bi = st + i; }
        }
        sxt[tid] = bi;
    }
    __syncthreads();

    // ---- pass 3: pred = L*(colsumW - sum_f Whalf[hot_f,:]) + b + t_emb[t] ----
    // fp16 gather (4 cols / thread, 8B loads), fp32 accumulate
    if (tid < D_VEC4) {
        const int cbase = tid * 4;
        float ax = 0.f, ay = 0.f, az = 0.f, aw = 0.f;
        #pragma unroll 8
        for (int f = 0; f < F_FEAT; ++f) {
            const __half* wr = g_Whalf + (size_t)sxt[f] * D_COLS + cbase;
            uint2 u = *reinterpret_cast<const uint2*>(wr);
            __half2 h0 = *reinterpret_cast<__half2*>(&u.x);
            __half2 h1 = *reinterpret_cast<__half2*>(&u.y);
            float2 f0 = __half22float2(h0);
            float2 f1 = __half22float2(h1);
            ax += f0.x; ay += f0.y; az += f1.x; aw += f1.y;
        }
        float4 cs = *reinterpret_cast<const float4*>(g_colsumW + cbase);
        float4 bb = *reinterpret_cast<const float4*>(bvec + cbase);
        float4 tt = *reinterpret_cast<const float4*>(temb + (size_t)t * D_COLS + cbase);
        P[cbase + 0] = LNEG * (cs.x - ax) + bb.x + tt.x;
        P[cbase + 1] = LNEG * (cs.y - ay) + bb.y + tt.y;
        P[cbase + 2] = LNEG * (cs.z - az) + bb.z + tt.z;
        P[cbase + 3] = LNEG * (cs.w - aw) + bb.w + tt.w;
    }
    __syncthreads();

    // ---- pass 4: seg logsumexp(pred) + closed-form un_true statistics ----
    if (tid < F_FEAT) {
        int st, nc, k;
        featinfo(tid, st, nc, k);
        float lognc = c_lognc[k];
        float m = P[st];
        for (int i = 1; i < nc; ++i) m = fmaxf(m, P[st + i]);
        float s = 0.f;
        for (int i = 0; i < nc; ++i) s += expf(P[st + i] - m);
        fl_pred[tid] = m + logf(s);

        // un_true = evT + qone takes <=3 distinct values per segment
        float qn = l1a_t - lognc;
        float qh = s_qh[tid];
        float en = t0 ? LNEG : (l1ca_m - lognc);
        float eh = t0 ? 0.f  : lap(lca_m, l1ca_m - lognc);
        int cs0 = sx0[tid], cst = sxt[tid];
        if (cst == cs0) {
            float Ub = eh + qh;
            float Un = en + qn;
            float mm = fmaxf(Ub, Un);
            float ss = expf(Ub - mm) + (float)(nc - 1) * expf(Un - mm);
            float lse1 = mm + logf(ss);
            float ltb = Ub - lse1, ltn = Un - lse1;
            s_ltT[tid] = ltb; s_pT[tid] = expf(ltb);
            s_lt0[tid] = ltb; s_p0[tid] = s_pT[tid];
            s_ltN[tid] = ltn; s_pN[tid] = expf(ltn);
        } else {
            float Ut = en + qh;
            float U0 = eh + qn;
            float Un = en + qn;
            float mm = fmaxf(fmaxf(Ut, U0), Un);
            float ss = expf(Ut - mm) + expf(U0 - mm) + (float)(nc - 2) * expf(Un - mm);
            float lse1 = mm + logf(ss);
            float ltt = Ut - lse1, lt0 = U0 - lse1, ltn = Un - lse1;
            s_ltT[tid] = ltt; s_pT[tid] = expf(ltt);
            s_lt0[tid] = lt0; s_p0[tid] = expf(lt0);
            s_ltN[tid] = ltn; s_pN[tid] = expf(ltn);
        }
    }
    __syncthreads();

    // ---- pass 5: U2 = evE + qone (per col; only evE needs a real lap) ----
    for (int c = tid; c < D_COLS; c += NTHREADS) {
        int feat; float lognc;
        colinfo(c, feat, lognc);
        float qone = (c == sxt[feat]) ? s_qh[feat] : (l1a_t - lognc);
        float x0h = P[c] - fl_pred[feat];
        float evE = t0 ? x0h : lap(x0h + lca_m, l1ca_m - lognc);
        P[c] = evE + qone;
    }
    __syncthreads();

    // ---- pass 6: seg lse of U2, dec term at hot-x0 col ----
    if (tid < F_FEAT) {
        int st, nc, k;
        featinfo(tid, st, nc, k);
        float m = P[st];
        for (int i = 1; i < nc; ++i) m = fmaxf(m, P[st + i]);
        float s = 0.f;
        for (int i = 0; i < nc; ++i) s += expf(P[st + i] - m);
        float lse2 = m + logf(s);
        fl_u2[tid] = lse2;
        s_dec[tid] = P[sx0[tid]] - lse2;    // log_est at hot x0 col
    }
    __syncthreads();

    // ---- pass 7: kl accumulation (pure FMA + selects) ----
    float kl = 0.f;
    for (int c = tid; c < D_COLS; c += NTHREADS) {
        int feat; float lognc;
        colinfo(c, feat, lognc);
        float le = P[c] - fl_u2[feat];
        float p, lt;
        if (c == sxt[feat])      { p = s_pT[feat]; lt = s_ltT[feat]; }
        else if (c == sx0[feat]) { p = s_p0[feat]; lt = s_lt0[feat]; }
        else                     { p = s_pN[feat]; lt = s_ltN[feat]; }
        kl += p * (lt - le);
    }
    #pragma unroll
    for (int o = 16; o > 0; o >>= 1)
        kl += __shfl_down_sync(0xffffffffu, kl, o);
    if ((tid & 31) == 0) rbuf[tid >> 5] = kl;
    __syncthreads();
    if (tid == 0) {
        float tkl = 0.f;
        #pragma unroll
        for (int w = 0; w < NTHREADS / 32; ++w) tkl += rbuf[w];
        float dec = 0.f, kp = g_kp_const;
        #pragma unroll 8
        for (int f = 0; f < F_FEAT; ++f) { dec += s_dec[f]; kp += s_kpf[f]; }
        float diff_loss = t0 ? (-dec) : tkl;
        g_partial[row] = diff_loss * (float)T_STEPS + kp;
    }
}

// ---------------- final deterministic mean reduction ----------------
__global__ void reduce_kernel(float* __restrict__ out) {
    __shared__ float s[1024];
    int tid = threadIdx.x;
    float acc = 0.f;
    for (int i = tid; i < B_ROWS; i += 1024) acc += g_partial[i];
    s[tid] = acc;
    __syncthreads();
    for (int off = 512; off > 0; off >>= 1) {
        if (tid < off) s[tid] += s[tid + off];
        __syncthreads();
    }
    if (tid == 0) out[0] = s[0] / (float)B_ROWS;
}

// ---------------- launch ----------------
extern "C" void kernel_launch(void* const* d_in, const int* in_sizes, int n_in,
                              void* d_out, int out_size) {
    // Identify inputs robustly by element count (all sizes distinct).
    const int*   x0   = nullptr;  // 32768*40
    const int*   ts   = nullptr;  // 32768
    const float* uni  = nullptr;  // 32768*496
    const float* W    = nullptr;  // 496*496
    const float* bvec = nullptr;  // 496
    const float* temb = nullptr;  // 1000*496
    for (int i = 0; i < n_in; ++i) {
        switch (in_sizes[i]) {
            case B_ROWS * F_FEAT:   x0   = (const int*)d_in[i];   break;
            case B_ROWS:            ts   = (const int*)d_in[i];   break;
            case B_ROWS * D_COLS:   uni  = (const float*)d_in[i]; break;
            case D_COLS * D_COLS:   W    = (const float*)d_in[i]; break;
            case D_COLS:            bvec = (const float*)d_in[i]; break;
            case T_STEPS * D_COLS:  temb = (const float*)d_in[i]; break;
            default: break;
        }
    }
    float* out = (float*)d_out;

    init_sched_kernel<<<1, 1024>>>();
    init_whalf_kernel<<<(D_COLS * D_COLS / 4 + 255) / 256, 256>>>(W);
    init_colsum_kernel<<<D_COLS / 4, NTHREADS>>>(W);
    ddpm_row_kernel<<<B_ROWS, NTHREADS>>>(x0, ts, uni, bvec, temb);
    reduce_kernel<<<1, 1024>>>(out);
}

// round 10
// speedup vs baseline: 1.5306x; 1.2952x over previous
#include <cuda_runtime.h>
#include <cuda_fp16.h>
#include <math.h>

// ---------------- static problem config ----------------
#define B_ROWS 32768
#define D_COLS 496
#define F_FEAT 40
#define T_STEPS 1000
#define NTHREADS 128
#define NSLOT 512            // padded layout: 8 groups x 64 slots (2 pad slots/group)

#define LNEG   (-69.07755279f)   // log(1e-30f)
#define NEGBIG (-1.0e30f)

// ---------------- device-global scratch ----------------
__device__ float g_log_alpha[T_STEPS];
__device__ float g_log_1m_alpha[T_STEPS];
__device__ float g_log_ca[T_STEPS];
__device__ float g_log_1m_ca[T_STEPS];
__device__ float g_colsumW[D_COLS];
__device__ float g_partial[B_ROWS];
__device__ float g_kp_const;
__device__ __align__(16) __half g_Whalf[D_COLS * D_COLS];

__constant__ float c_lognc[5] = {
    0.69314718055994530942f,
    1.38629436111989061883f,
    2.07944154167983592825f,
    2.77258872223978123767f,
    3.46573590279972654709f
};

// fast logaddexp: max + log1p(exp(-|d|)); exact collapse when gap < -56
__device__ __forceinline__ float lap2(float a, float b) {
    float m = fmaxf(a, b);
    return m + __logf(1.0f + __expf(-fabsf(a - b)));
}

// slot metadata: slot s in padded layout. group g = s>>6, r = s&63.
// r in [nc, 2nc) belongs to segment of size nc (nc = 2,4,8,16,32); r<2 = padding.
struct SlotMeta { int s, g, r, k, nc, feat; bool pad; float lognc; };
__device__ __forceinline__ SlotMeta slotmeta(int tid, int i) {
    SlotMeta M;
    M.s = tid + NTHREADS * i;
    M.g = M.s >> 6;
    M.r = M.s & 63;
    M.pad = M.r < 2;
    int pos = 31 - __clz(M.r | 2);   // 1..5
    M.k = pos - 1;
    M.nc = 1 << pos;
    M.feat = M.g * 5 + M.k;
    M.lognc = c_lognc[M.k];
    return M;
}

// segmented butterfly primitives (segments are lane-aligned, size nc)
__device__ __forceinline__ float bfly_max(float v, int nc) {
    #pragma unroll
    for (int off = 1; off < 32; off <<= 1) {
        float o = __shfl_xor_sync(0xffffffffu, v, off);
        if (off < nc) v = fmaxf(v, o);
    }
    return v;
}
__device__ __forceinline__ float bfly_sum(float v, int nc) {
    #pragma unroll
    for (int off = 1; off < 32; off <<= 1) {
        float o = __shfl_xor_sync(0xffffffffu, v, off);
        if (off < nc) v += o;
    }
    return v;
}
__device__ __forceinline__ void bfly_sum2(float& a, float& b, int nc) {
    #pragma unroll
    for (int off = 1; off < 32; off <<= 1) {
        float oa = __shfl_xor_sync(0xffffffffu, a, off);
        float ob = __shfl_xor_sync(0xffffffffu, b, off);
        if (off < nc) { a += oa; b += ob; }
    }
}

// ---------------- init: diffusion schedules (f64) ----------------
__global__ void init_sched_kernel() {
    __shared__ double s[1024];
    int t = threadIdx.x;
    double la = 0.0;
    if (t < T_STEPS) {
        double beta = 1e-4 + (0.02 - 1e-4) * ((double)t / (double)(T_STEPS - 1));
        double alpha = 1.0 - beta;
        la = log(alpha);
        g_log_alpha[t]    = (float)la;
        g_log_1m_alpha[t] = (float)log(1.0 - alpha);
    }
    s[t] = (t < T_STEPS) ? la : 0.0;
    __syncthreads();
    for (int off = 1; off < 1024; off <<= 1) {
        double v = (t >= off) ? s[t - off] : 0.0;
        __syncthreads();
        s[t] += v;
        __syncthreads();
    }
    if (t < T_STEPS) {
        double cs = s[t];
        g_log_ca[t]    = (float)cs;
        g_log_1m_ca[t] = (float)log(-expm1(cs));
    }
    __syncthreads();
    if (t == 0) {
        float l1caT = g_log_1m_ca[T_STEPS - 1];
        float acc = 0.f;
        #pragma unroll
        for (int k = 0; k < 5; ++k) {
            int nc = 2 << k;
            acc += 8.f * (float)(nc - 1) * expf(l1caT - c_lognc[k]) * l1caT;
        }
        g_kp_const = acc;
    }
}

// ---------------- init: fp16 copy of W ----------------
__global__ void init_whalf_kernel(const float* __restrict__ W) {
    int i = (blockIdx.x * blockDim.x + threadIdx.x) * 4;
    if (i < D_COLS * D_COLS) {
        float4 v = *reinterpret_cast<const float4*>(W + i);
        *reinterpret_cast<__half2*>(&g_Whalf[i])     = __floats2half2_rn(v.x, v.y);
        *reinterpret_cast<__half2*>(&g_Whalf[i + 2]) = __floats2half2_rn(v.z, v.w);
    }
}

// ---------------- init: column sums of W (fp32) ----------------
__global__ void init_colsum_kernel(const float* __restrict__ W) {
    __shared__ float4 sb[NTHREADS];
    int g4 = blockIdx.x * 4;
    int tid = threadIdx.x;
    float4 acc = make_float4(0.f, 0.f, 0.f, 0.f);
    for (int r = tid; r < D_COLS; r += NTHREADS) {
        float4 v = *reinterpret_cast<const float4*>(W + (size_t)r * D_COLS + g4);
        acc.x += v.x; acc.y += v.y; acc.z += v.z; acc.w += v.w;
    }
    sb[tid] = acc;
    __syncthreads();
    for (int off = NTHREADS / 2; off > 0; off >>= 1) {
        if (tid < off) {
            float4 o = sb[tid + off];
            sb[tid].x += o.x; sb[tid].y += o.y; sb[tid].z += o.z; sb[tid].w += o.w;
        }
        __syncthreads();
    }
    if (tid == 0) *reinterpret_cast<float4*>(g_colsumW + g4) = sb[0];
}

// ---------------- main: one block per batch row ----------------
__global__ __launch_bounds__(NTHREADS) void ddpm_row_kernel(
    const int*   __restrict__ x0,
    const int*   __restrict__ ts,
    const float* __restrict__ uni,
    const float* __restrict__ bvec,
    const float* __restrict__ temb)
{
    __shared__ float Ppad[NSLOT];        // pred in padded slots
    __shared__ float Zpad[NSLOT];        // U2 values for point lookup
    __shared__ int   sx0_slot[F_FEAT];
    __shared__ int   s_xtcol[F_FEAT];    // xt winner as ORIGINAL column (for W gather)
    __shared__ float s_hot1[F_FEAT];     // hot q_prior value
    __shared__ float s_qh[F_FEAT];       // hot q_one value
    __shared__ float s_kpf[F_FEAT];      // hot kl_prior term
    __shared__ float rbuf[3][NTHREADS / 32];

    const int row = blockIdx.x;
    const int tid = threadIdx.x;
    const int lane = tid & 31;

    const int t   = ts[row];
    const int tm1 = max(t - 1, 0);
    const float la_t   = g_log_alpha[t];
    const float l1a_t  = g_log_1m_alpha[t];
    const float lca_t  = g_log_ca[t];
    const float l1ca_t = g_log_1m_ca[t];
    const float lca_m  = g_log_ca[tm1];
    const float l1ca_m = g_log_1m_ca[tm1];
    const float lca_T  = g_log_ca[T_STEPS - 1];
    const float l1ca_T = g_log_1m_ca[T_STEPS - 1];
    const bool  t0 = (t == 0);

    // ---- setup: per-feature scalars (40 threads) ----
    if (tid < F_FEAT) {
        int gg = tid / 5, kk = tid - gg * 5;
        int nc = 2 << kk;
        float lognc = c_lognc[kk];
        sx0_slot[tid] = gg * 64 + nc + x0[row * F_FEAT + tid];
        s_hot1[tid] = lap2(lca_t, l1ca_t - lognc);
        s_qh[tid]   = lap2(la_t,  l1a_t  - lognc);
        float lqh = lap2(lca_T, l1ca_T - lognc);
        s_kpf[tid] = __expf(lqh) * (lqh + lognc);
    }
    __syncthreads();

    // ---- phase 1: gumbel z + segmented first-max argmax (registers only) ----
    int ws[4];
    #pragma unroll
    for (int i = 0; i < 4; ++i) {
        SlotMeta M = slotmeta(tid, i);
        float z;
        if (!M.pad) {
            int c = M.s - 2 * M.g - 2;
            float u = uni[(size_t)row * D_COLS + c];
            float gmb = -__logf(-__logf(u + 1e-30f) + 1e-30f);
            float lp = (M.s == sx0_slot[M.feat]) ? s_hot1[M.feat]
                                                 : (l1ca_t - M.lognc);
            z = gmb + lp;
        } else {
            z = NEGBIG;
        }
        float m = bfly_max(z, M.nc);
        unsigned bal = __ballot_sync(0xffffffffu, (z == m) && !M.pad);
        int lanebase = (M.s & 32) ? 0 : M.nc;   // high block: whole warp; low: [nc,2nc)
        unsigned segmask = (M.nc == 32) ? 0xffffffffu
                                        : (((1u << M.nc) - 1u) << lanebase);
        int wl = __ffs(bal & segmask) - 1;      // first max = smallest index
        ws[i] = (M.s - lane) + wl;
        if (M.r == M.nc) {                      // segment leader
            int wsl = ws[i];
            s_xtcol[M.feat] = wsl - 2 * (wsl >> 6) - 2;
        }
    }
    __syncthreads();

    // ---- phase 2: pred gather (dense layout, fp16 W, fp32 accumulate) ----
    if (tid < 124) {
        const int cbase = tid * 4;
        float ax = 0.f, ay = 0.f, az = 0.f, aw = 0.f;
        #pragma unroll 8
        for (int f = 0; f < F_FEAT; ++f) {
            const __half* wr = g_Whalf + (size_t)s_xtcol[f] * D_COLS + cbase;
            uint2 uu = *reinterpret_cast<const uint2*>(wr);
            __half2 h0 = *reinterpret_cast<__half2*>(&uu.x);
            __half2 h1 = *reinterpret_cast<__half2*>(&uu.y);
            float2 f0 = __half22float2(h0);
            float2 f1 = __half22float2(h1);
            ax += f0.x; ay += f0.y; az += f1.x; aw += f1.y;
        }
        float4 cs = *reinterpret_cast<const float4*>(g_colsumW + cbase);
        float4 bb = *reinterpret_cast<const float4*>(bvec + cbase);
        float4 tt = *reinterpret_cast<const float4*>(temb + (size_t)t * D_COLS + cbase);
        float pv0 = LNEG * (cs.x - ax) + bb.x + tt.x;
        float pv1 = LNEG * (cs.y - ay) + bb.y + tt.y;
        float pv2 = LNEG * (cs.z - az) + bb.z + tt.z;
        float pv3 = LNEG * (cs.w - aw) + bb.w + tt.w;
        int c0 = cbase;
        Ppad[c0 + 2 * (c0 / 62) + 2]     = pv0;
        Ppad[c0 + 1 + 2 * ((c0 + 1) / 62) + 2] = pv1;
        Ppad[c0 + 2 + 2 * ((c0 + 2) / 62) + 2] = pv2;
        Ppad[c0 + 3 + 2 * ((c0 + 3) / 62) + 2] = pv3;
    }
    __syncthreads();

    // ---- phase 3: softmax lse, U2 = evE + qone, lse2/sumU2, per-feature kl ----
    float kl_acc = 0.f, dec_acc = 0.f, kp_acc = 0.f;
    #pragma unroll
    for (int i = 0; i < 4; ++i) {
        SlotMeta M = slotmeta(tid, i);
        float p = M.pad ? NEGBIG : Ppad[M.s];
        float m = bfly_max(p, M.nc);
        float e = M.pad ? 0.f : __expf(p - m);
        float S = bfly_sum(e, M.nc);
        float lse1 = m + __logf(S);

        float qn = l1a_t - M.lognc;
        float U2, u2m;
        if (!M.pad) {
            float x0h = p - lse1;                               // log_x0_hat
            float evE = t0 ? x0h : lap2(x0h + lca_m, l1ca_m - M.lognc);
            float qone = (M.s == ws[i]) ? s_qh[M.feat] : qn;
            U2 = evE + qone;
            u2m = U2;
        } else {
            U2 = 0.f;
            u2m = NEGBIG;
        }
        Zpad[M.s] = U2;
        float m2 = bfly_max(u2m, M.nc);
        float e2 = M.pad ? 0.f : __expf(U2 - m2);
        float S2 = e2, SU = M.pad ? 0.f : U2;
        bfly_sum2(S2, SU, M.nc);                                // sum exp + sum U2
        float lse2 = m2 + __logf(S2);
        __syncwarp();

        if (M.r == M.nc) {                                      // segment leader
            int f = M.feat;
            int cs0 = sx0_slot[f];
            int cst = ws[i];
            float U2x0 = Zpad[cs0];
            float U2xt = Zpad[cst];
            float lognc = M.lognc;
            float qh = s_qh[f];
            float en = t0 ? LNEG : (l1ca_m - lognc);
            float eh = t0 ? 0.f  : lap2(lca_m, l1ca_m - lognc);
            float ncf = (float)M.nc;
            float Sp_lt, sum_pU2;
            if (cst == cs0) {
                float Ub = eh + qh, Un = en + qn;
                float mm = fmaxf(Ub, Un);
                float ss = __expf(Ub - mm) + (ncf - 1.f) * __expf(Un - mm);
                float lset = mm + __logf(ss);
                float ltb = Ub - lset, ltn = Un - lset;
                float pT = __expf(ltb), pN = __expf(ltn);
                Sp_lt  = pT * ltb + (ncf - 1.f) * pN * ltn;
                sum_pU2 = pN * SU + (pT - pN) * U2xt;
            } else {
                float Ut = en + qh, U0 = eh + qn, Un = en + qn;
                float mm = fmaxf(fmaxf(Ut, U0), Un);
                float ss = __expf(Ut - mm) + __expf(U0 - mm)
                         + (ncf - 2.f) * __expf(Un - mm);
                float lset = mm + __logf(ss);
                float ltt = Ut - lset, lt0 = U0 - lset, ltn = Un - lset;
                float pT = __expf(ltt), p0 = __expf(lt0), pN = __expf(ltn);
                Sp_lt  = pT * ltt + p0 * lt0 + (ncf - 2.f) * pN * ltn;
                sum_pU2 = pN * SU + (pT - pN) * U2xt + (p0 - pN) * U2x0;
            }
            kl_acc  += Sp_lt + lse2 - sum_pU2;   // sum_c p*(lt - le), le = U2 - lse2
            dec_acc += U2x0 - lse2;              // log_est at hot x0 col
            kp_acc  += s_kpf[f];
        }
    }

    // ---- final per-row reduction ----
    #pragma unroll
    for (int o = 16; o > 0; o >>= 1) {
        kl_acc  += __shfl_xor_sync(0xffffffffu, kl_acc,  o);
        dec_acc += __shfl_xor_sync(0xffffffffu, dec_acc, o);
        kp_acc  += __shfl_xor_sync(0xffffffffu, kp_acc,  o);
    }
    if (lane == 0) {
        rbuf[0][tid >> 5] = kl_acc;
        rbuf[1][tid >> 5] = dec_acc;
        rbuf[2][tid >> 5] = kp_acc;
    }
    __syncthreads();
    if (tid == 0) {
        float tkl = 0.f, tdec = 0.f, tkp = 0.f;
        #pragma unroll
        for (int w = 0; w < NTHREADS / 32; ++w) {
            tkl += rbuf[0][w]; tdec += rbuf[1][w]; tkp += rbuf[2][w];
        }
        float diff_loss = t0 ? (-tdec) : tkl;
        g_partial[row] = diff_loss * (float)T_STEPS + tkp + g_kp_const;
    }
}

// ---------------- final deterministic mean reduction ----------------
__global__ void reduce_kernel(float* __restrict__ out) {
    __shared__ float s[1024];
    int tid = threadIdx.x;
    float acc = 0.f;
    for (int i = tid; i < B_ROWS; i += 1024) acc += g_partial[i];
    s[tid] = acc;
    __syncthreads();
    for (int off = 512; off > 0; off >>= 1) {
        if (tid < off) s[tid] += s[tid + off];
        __syncthreads();
    }
    if (tid == 0) out[0] = s[0] / (float)B_ROWS;
}

// ---------------- launch ----------------
extern "C" void kernel_launch(void* const* d_in, const int* in_sizes, int n_in,
                              void* d_out, int out_size) {
    const int*   x0   = nullptr;
    const int*   ts   = nullptr;
    const float* uni  = nullptr;
    const float* W    = nullptr;
    const float* bvec = nullptr;
    const float* temb = nullptr;
    for (int i = 0; i < n_in; ++i) {
        switch (in_sizes[i]) {
            case B_ROWS * F_FEAT:   x0   = (const int*)d_in[i];   break;
            case B_ROWS:            ts   = (const int*)d_in[i];   break;
            case B_ROWS * D_COLS:   uni  = (const float*)d_in[i]; break;
            case D_COLS * D_COLS:   W    = (const float*)d_in[i]; break;
            case D_COLS:            bvec = (const float*)d_in[i]; break;
            case T_STEPS * D_COLS:  temb = (const float*)d_in[i]; break;
            default: break;
        }
    }
    float* out = (float*)d_out;

    init_sched_kernel<<<1, 1024>>>();
    init_whalf_kernel<<<(D_COLS * D_COLS / 4 + 255) / 256, 256>>>(W);
    init_colsum_kernel<<<D_COLS / 4, NTHREADS>>>(W);
    ddpm_row_kernel<<<B_ROWS, NTHREADS>>>(x0, ts, uni, bvec, temb);
    reduce_kernel<<<1, 1024>>>(out);
}

// round 16
// speedup vs baseline: 1.6688x; 1.0903x over previous
#include <cuda_runtime.h>
#include <cuda_fp16.h>
#include <math.h>

// ---------------- static problem config ----------------
#define B_ROWS 32768
#define D_COLS 496
#define F_FEAT 40
#define T_STEPS 1000
#define NTHREADS 128
#define NSLOT 512            // padded layout: 8 groups x 64 slots (2 pad slots/group)

#define LNEG   (-69.07755279f)   // log(1e-30f)
#define NEGBIG (-1.0e30f)

// ---------------- device-global scratch ----------------
__device__ float g_log_alpha[T_STEPS];
__device__ float g_log_1m_alpha[T_STEPS];
__device__ float g_log_ca[T_STEPS];
__device__ float g_log_1m_ca[T_STEPS];
__device__ float g_colsumW[D_COLS];
__device__ float g_partial[B_ROWS];
__device__ float g_kp_const;
__device__ __align__(16) __half g_Whalf[D_COLS * D_COLS];

__constant__ float c_lognc[5] = {
    0.69314718055994530942f,
    1.38629436111989061883f,
    2.07944154167983592825f,
    2.77258872223978123767f,
    3.46573590279972654709f
};

// fast logaddexp: max + log1p(exp(-|d|)); exact collapse when gap < -56
__device__ __forceinline__ float lap2(float a, float b) {
    float m = fmaxf(a, b);
    return m + __logf(1.0f + __expf(-fabsf(a - b)));
}

// slot metadata: slot s in padded layout. group g = s>>6, r = s&63.
// r in [nc, 2nc) belongs to segment of size nc (nc = 2,4,8,16,32); r<2 = padding.
struct SlotMeta { int s, g, r, k, nc, feat; bool pad; float lognc; };
__device__ __forceinline__ SlotMeta slotmeta(int tid, int i) {
    SlotMeta M;
    M.s = tid + NTHREADS * i;
    M.g = M.s >> 6;
    M.r = M.s & 63;
    M.pad = M.r < 2;
    int pos = 31 - __clz(M.r | 2);   // 1..5
    M.k = pos - 1;
    M.nc = 1 << pos;
    M.feat = M.g * 5 + M.k;
    M.lognc = c_lognc[M.k];
    return M;
}

// segmented butterfly primitives (segments are lane-aligned, size nc)
__device__ __forceinline__ float bfly_max(float v, int nc) {
    #pragma unroll
    for (int off = 1; off < 32; off <<= 1) {
        float o = __shfl_xor_sync(0xffffffffu, v, off);
        if (off < nc) v = fmaxf(v, o);
    }
    return v;
}
__device__ __forceinline__ float bfly_sum(float v, int nc) {
    #pragma unroll
    for (int off = 1; off < 32; off <<= 1) {
        float o = __shfl_xor_sync(0xffffffffu, v, off);
        if (off < nc) v += o;
    }
    return v;
}
__device__ __forceinline__ void bfly_sum2(float& a, float& b, int nc) {
    #pragma unroll
    for (int off = 1; off < 32; off <<= 1) {
        float oa = __shfl_xor_sync(0xffffffffu, a, off);
        float ob = __shfl_xor_sync(0xffffffffu, b, off);
        if (off < nc) { a += oa; b += ob; }
    }
}

// ---------------- combined init: block 0 = schedules (f64), blocks 1..124 = colsum + fp16 W copy
__global__ void init_combined_kernel(const float* __restrict__ W) {
    __shared__ double sd[1024];
    __shared__ float4 sb[1024];
    const int tid = threadIdx.x;

    if (blockIdx.x == 0) {
        // ---- diffusion schedules (f64, matching numpy) ----
        int t = tid;
        double la = 0.0;
        if (t < T_STEPS) {
            double beta = 1e-4 + (0.02 - 1e-4) * ((double)t / (double)(T_STEPS - 1));
            double alpha = 1.0 - beta;
            la = log(alpha);
            g_log_alpha[t]    = (float)la;
            g_log_1m_alpha[t] = (float)log(1.0 - alpha);
        }
        sd[t] = (t < T_STEPS) ? la : 0.0;
        __syncthreads();
        for (int off = 1; off < 1024; off <<= 1) {
            double v = (t >= off) ? sd[t - off] : 0.0;
            __syncthreads();
            sd[t] += v;
            __syncthreads();
        }
        if (t < T_STEPS) {
            double cs = sd[t];
            g_log_ca[t]    = (float)cs;
            g_log_1m_ca[t] = (float)log(-expm1(cs));
        }
        __syncthreads();
        if (t == 0) {
            float l1caT = g_log_1m_ca[T_STEPS - 1];
            float acc = 0.f;
            #pragma unroll
            for (int k = 0; k < 5; ++k) {
                int nc = 2 << k;
                acc += 8.f * (float)(nc - 1) * expf(l1caT - c_lognc[k]) * l1caT;
            }
            g_kp_const = acc;
        }
    } else {
        const int b = blockIdx.x - 1;   // 0..123
        // ---- fp16 copy slice ----
        int idx = (b * 1024 + tid) * 4;
        if (idx < D_COLS * D_COLS) {
            float4 v = *reinterpret_cast<const float4*>(W + idx);
            *reinterpret_cast<__half2*>(&g_Whalf[idx])     = __floats2half2_rn(v.x, v.y);
            *reinterpret_cast<__half2*>(&g_Whalf[idx + 2]) = __floats2half2_rn(v.z, v.w);
        }
        // ---- column sums for columns [4b, 4b+4) ----
        int g4 = b * 4;
        float4 acc = make_float4(0.f, 0.f, 0.f, 0.f);
        for (int r = tid; r < D_COLS; r += 1024) {
            float4 v = *reinterpret_cast<const float4*>(W + (size_t)r * D_COLS + g4);
            acc.x += v.x; acc.y += v.y; acc.z += v.z; acc.w += v.w;
        }
        sb[tid] = acc;
        __syncthreads();
        for (int off = 512; off > 0; off >>= 1) {
            if (tid < off) {
                float4 o = sb[tid + off];
                sb[tid].x += o.x; sb[tid].y += o.y; sb[tid].z += o.z; sb[tid].w += o.w;
            }
            __syncthreads();
        }
        if (tid == 0) *reinterpret_cast<float4*>(g_colsumW + g4) = sb[0];
    }
}

// ---------------- main: one block per batch row ----------------
__global__ __launch_bounds__(NTHREADS) void ddpm_row_kernel(
    const int*   __restrict__ x0,
    const int*   __restrict__ ts,
    const float* __restrict__ uni,
    const float* __restrict__ bvec,
    const float* __restrict__ temb)
{
    __shared__ float Ppad[NSLOT];        // pred in padded slots
    __shared__ float Zpad[NSLOT];        // U2 values for point lookup
    __shared__ int   sx0_slot[F_FEAT];
    __shared__ int   s_xtcol[F_FEAT];    // xt winner as ORIGINAL column (for W gather)
    __shared__ float s_hot1[F_FEAT];     // hot q_prior value
    __shared__ float s_qh[F_FEAT];       // hot q_one value
    __shared__ float s_kpf[F_FEAT];      // hot kl_prior term
    __shared__ float rbuf[3][NTHREADS / 32];

    const int row = blockIdx.x;
    const int tid = threadIdx.x;
    const int lane = tid & 31;

    const int t   = ts[row];
    const int tm1 = max(t - 1, 0);
    const float la_t   = g_log_alpha[t];
    const float l1a_t  = g_log_1m_alpha[t];
    const float lca_t  = g_log_ca[t];
    const float l1ca_t = g_log_1m_ca[t];
    const float lca_m  = g_log_ca[tm1];
    const float l1ca_m = g_log_1m_ca[tm1];
    const float lca_T  = g_log_ca[T_STEPS - 1];
    const float l1ca_T = g_log_1m_ca[T_STEPS - 1];
    const bool  t0 = (t == 0);

    // ---- setup: per-feature scalars (40 threads) ----
    if (tid < F_FEAT) {
        int gg = tid / 5, kk = tid - gg * 5;
        int nc = 2 << kk;
        float lognc = c_lognc[kk];
        sx0_slot[tid] = gg * 64 + nc + x0[row * F_FEAT + tid];
        s_hot1[tid] = lap2(lca_t, l1ca_t - lognc);
        s_qh[tid]   = lap2(la_t,  l1a_t  - lognc);
        float lqh = lap2(lca_T, l1ca_T - lognc);
        s_kpf[tid] = __expf(lqh) * (lqh + lognc);
    }
    __syncthreads();

    // ---- phase 1: gumbel z + segmented first-max argmax (registers only) ----
    int ws[4];
    #pragma unroll
    for (int i = 0; i < 4; ++i) {
        SlotMeta M = slotmeta(tid, i);
        float z;
        if (!M.pad) {
            int c = M.s - 2 * M.g - 2;
            float u = uni[(size_t)row * D_COLS + c];
            float gmb = -__logf(-__logf(u + 1e-30f) + 1e-30f);
            float lp = (M.s == sx0_slot[M.feat]) ? s_hot1[M.feat]
                                                 : (l1ca_t - M.lognc);
            z = gmb + lp;
        } else {
            z = NEGBIG;
        }
        float m = bfly_max(z, M.nc);
        unsigned bal = __ballot_sync(0xffffffffu, (z == m) && !M.pad);
        int lanebase = (M.s & 32) ? 0 : M.nc;   // high block: whole warp; low: [nc,2nc)
        unsigned segmask = (M.nc == 32) ? 0xffffffffu
                                        : (((1u << M.nc) - 1u) << lanebase);
        int wl = __ffs(bal & segmask) - 1;      // first max = smallest index
        ws[i] = (M.s - lane) + wl;
        if (M.r == M.nc) {                      // segment leader
            int wsl = ws[i];
            s_xtcol[M.feat] = wsl - 2 * (wsl >> 6) - 2;
        }
    }
    __syncthreads();

    // ---- phase 2: pred gather (fp16 W, HADD2 accumulate in blocks of 8) ----
    if (tid < 124) {
        const int cbase = tid * 4;
        const __half* wbase = g_Whalf + cbase;
        __half2 h2a = __float2half2_rn(0.f);
        __half2 h2b = __float2half2_rn(0.f);
        float ax = 0.f, ay = 0.f, az = 0.f, aw = 0.f;
        #pragma unroll
        for (int f = 0; f < F_FEAT; ++f) {
            const __half* wr = wbase + (size_t)s_xtcol[f] * D_COLS;
            uint2 uu = *reinterpret_cast<const uint2*>(wr);
            h2a = __hadd2(h2a, *reinterpret_cast<__half2*>(&uu.x));
            h2b = __hadd2(h2b, *reinterpret_cast<__half2*>(&uu.y));
            if ((f & 7) == 7) {                     // dump every 8 features
                float2 fa = __half22float2(h2a);
                float2 fb = __half22float2(h2b);
                ax += fa.x; ay += fa.y; az += fb.x; aw += fb.y;
                h2a = __float2half2_rn(0.f);
                h2b = __float2half2_rn(0.f);
            }
        }
        float4 cs = *reinterpret_cast<const float4*>(g_colsumW + cbase);
        float4 bb = *reinterpret_cast<const float4*>(bvec + cbase);
        float4 tt = *reinterpret_cast<const float4*>(temb + (size_t)t * D_COLS + cbase);
        float pv0 = LNEG * (cs.x - ax) + bb.x + tt.x;
        float pv1 = LNEG * (cs.y - ay) + bb.y + tt.y;
        float pv2 = LNEG * (cs.z - az) + bb.z + tt.z;
        float pv3 = LNEG * (cs.w - aw) + bb.w + tt.w;
        int c0 = cbase;
        Ppad[c0 + 2 * (c0 / 62) + 2]           = pv0;
        Ppad[c0 + 1 + 2 * ((c0 + 1) / 62) + 2] = pv1;
        Ppad[c0 + 2 + 2 * ((c0 + 2) / 62) + 2] = pv2;
        Ppad[c0 + 3 + 2 * ((c0 + 3) / 62) + 2] = pv3;
    }
    __syncthreads();

    // ---- phase 3: softmax lse, U2 = evE + qone, lse2/sumU2, per-feature kl ----
    float kl_acc = 0.f, dec_acc = 0.f, kp_acc = 0.f;
    #pragma unroll
    for (int i = 0; i < 4; ++i) {
        SlotMeta M = slotmeta(tid, i);
        float p = M.pad ? NEGBIG : Ppad[M.s];
        float m = bfly_max(p, M.nc);
        float e = M.pad ? 0.f : __expf(p - m);
        float S = bfly_sum(e, M.nc);
        float lse1 = m + __logf(S);

        float qn = l1a_t - M.lognc;
        float U2 = NEGBIG;
        float e2 = 0.f, SUc = 0.f;
        if (!M.pad) {
            float x0h = p - lse1;                               // log_x0_hat
            float evE = t0 ? x0h : lap2(x0h + lca_m, l1ca_m - M.lognc);
            float qone = (M.s == ws[i]) ? s_qh[M.feat] : qn;
            U2 = evE + qone;
            // U2 <= ~0.7 (no overflow); segment max >= ~-30 (no fatal underflow)
            e2 = __expf(U2);
            SUc = U2;
        }
        Zpad[M.s] = U2;
        float S2 = e2, SU = SUc;
        bfly_sum2(S2, SU, M.nc);                                // sum exp + sum U2
        float lse2 = __logf(S2);
        __syncwarp();

        if (M.r == M.nc) {                                      // segment leader (branchless form)
            int f = M.feat;
            int cs0 = sx0_slot[f];
            int cst = ws[i];
            float U2x0 = Zpad[cs0];
            float U2xt = Zpad[cst];
            float lognc = M.lognc;
            float qh = s_qh[f];
            float en = t0 ? LNEG : (l1ca_m - lognc);
            float eh = t0 ? 0.f  : lap2(lca_m, l1ca_m - lognc);
            float ncf = (float)M.nc;
            bool  hot0 = (cst == cs0);
            float w0 = hot0 ? 0.f : 1.f;
            float U_xt = (hot0 ? eh : en) + qh;
            float U_x0 = eh + qn;
            float U_n  = en + qn;
            float mm = fmaxf(fmaxf(U_xt, U_n), U_x0);
            float eT = __expf(U_xt - mm);
            float e0 = __expf(U_x0 - mm);
            float eN = __expf(U_n  - mm);
            float wN = ncf - 1.f - w0;
            float ss = eT + w0 * e0 + wN * eN;
            float rs = __frcp_rn(ss);
            float lset = mm + __logf(ss);
            float ltT = U_xt - lset, lt0 = U_x0 - lset, ltn = U_n - lset;
            float pT = eT * rs, p0 = e0 * rs, pN = eN * rs;
            float Sp_lt   = pT * ltT + w0 * (p0 * lt0) + wN * (pN * ltn);
            float sum_pU2 = pN * SU + (pT - pN) * U2xt + w0 * ((p0 - pN) * U2x0);
            kl_acc  += Sp_lt + lse2 - sum_pU2;   // sum_c p*(lt - le), le = U2 - lse2
            dec_acc += U2x0 - lse2;              // log_est at hot x0 col
            kp_acc  += s_kpf[f];
        }
    }

    // ---- final per-row reduction ----
    #pragma unroll
    for (int o = 16; o > 0; o >>= 1) {
        kl_acc  += __shfl_xor_sync(0xffffffffu, kl_acc,  o);
        dec_acc += __shfl_xor_sync(0xffffffffu, dec_acc, o);
        kp_acc  += __shfl_xor_sync(0xffffffffu, kp_acc,  o);
    }
    if (lane == 0) {
        rbuf[0][tid >> 5] = kl_acc;
        rbuf[1][tid >> 5] = dec_acc;
        rbuf[2][tid >> 5] = kp_acc;
    }
    __syncthreads();
    if (tid == 0) {
        float tkl = 0.f, tdec = 0.f, tkp = 0.f;
        #pragma unroll
        for (int w = 0; w < NTHREADS / 32; ++w) {
            tkl += rbuf[0][w]; tdec += rbuf[1][w]; tkp += rbuf[2][w];
        }
        float diff_loss = t0 ? (-tdec) : tkl;
        g_partial[row] = diff_loss * (float)T_STEPS + tkp + g_kp_const;
    }
}

// ---------------- final deterministic mean reduction ----------------
__global__ void reduce_kernel(float* __restrict__ out) {
    __shared__ float s[1024];
    int tid = threadIdx.x;
    float acc = 0.f;
    const float4* p4 = reinterpret_cast<const float4*>(g_partial);
    for (int i = tid; i < B_ROWS / 4; i += 1024) {
        float4 v = p4[i];
        acc += (v.x + v.y) + (v.z + v.w);
    }
    s[tid] = acc;
    __syncthreads();
    for (int off = 512; off > 0; off >>= 1) {
        if (tid < off) s[tid] += s[tid + off];
        __syncthreads();
    }
    if (tid == 0) out[0] = s[0] / (float)B_ROWS;
}

// ---------------- launch ----------------
extern "C" void kernel_launch(void* const* d_in, const int* in_sizes, int n_in,
                              void* d_out, int out_size) {
    const int*   x0   = nullptr;
    const int*   ts   = nullptr;
    const float* uni  = nullptr;
    const float* W    = nullptr;
    const float* bvec = nullptr;
    const float* temb = nullptr;
    for (int i = 0; i < n_in; ++i) {
        switch (in_sizes[i]) {
            case B_ROWS * F_FEAT:   x0   = (const int*)d_in[i];   break;
            case B_ROWS:            ts   = (const int*)d_in[i];   break;
            case B_ROWS * D_COLS:   uni  = (const float*)d_in[i]; break;
            case D_COLS * D_COLS:   W    = (const float*)d_in[i]; break;
            case D_COLS:            bvec = (const float*)d_in[i]; break;
            case T_STEPS * D_COLS:  temb = (const float*)d_in[i]; break;
            default: break;
        }
    }
    float* out = (float*)d_out;

    init_combined_kernel<<<125, 1024>>>(W);
    ddpm_row_kernel<<<B_ROWS, NTHREADS>>>(x0, ts, uni, bvec, temb);
    reduce_kernel<<<1, 1024>>>(out);
}